// round 8
// baseline (speedup 1.0000x reference)
#include <cuda_runtime.h>
#include <cstdint>

// TopK-magnitude masking per row. x: (4096, 8192) fp32, K = 819.
// out[r,c] = x[r,c] if |x[r,c]| >= (K-th largest |x| in row r) else 0.
//
// One CTA per row, 512 threads, row staged in SMEM (<=32 regs -> 4 CTAs/SM).
// Exact K-th largest |x| via 3-pass radix select (11+10+10 bits) on bits(|x|).
// Sweep structure (2 full-row sweeps only):
//   sweep 1: LDG -> STS + pass-1 histogram
//   sweep 2: LDS -> FINAL STG (decided elements) + pass-2 histogram +
//            warp-aggregated compaction of undecided candidates (dig == d1)
//   pass 3 + fixup touch only the ~C compacted candidates.

#define ROWLEN  8192
#define TPB     512
#define VPT     4            // float4 per thread -> 16 floats
#define KSEL    819u
#define NW      (TPB / 32)   // 16 warps
#define CANDMAX 1024

// Suffix-scan + digit select over hist[NBINS].
// Outputs *sh_digit, *sh_k (rank within digit), *sh_cnt (digit count).
// Ends with __syncthreads.
template <int NBINS>
__device__ __forceinline__ void suffix_select(
    const unsigned* __restrict__ hist, unsigned k,
    int t, int lane, int wid,
    unsigned* wsum, unsigned* wtail,
    unsigned* sh_digit, unsigned* sh_k, unsigned* sh_cnt)
{
    constexpr int B = NBINS / TPB;        // bins per thread (4 or 2)
    const int base = t * B;
    unsigned loc[B];
    unsigned s = 0u;
#pragma unroll
    for (int j = B - 1; j >= 0; j--) { s += hist[base + j]; loc[j] = s; }

    unsigned p = s;                        // warp suffix scan of chunk totals
#pragma unroll
    for (int off = 1; off < 32; off <<= 1) {
        unsigned n = __shfl_down_sync(0xFFFFFFFFu, p, off);
        if (lane < 32 - off) p += n;
    }
    if (lane == 0) wsum[wid] = p;
    __syncthreads();
    if (t < NW) {
        unsigned q = wsum[t];
        unsigned r = q;
#pragma unroll
        for (int off = 1; off < NW; off <<= 1) {
            unsigned n = __shfl_down_sync(0x0000FFFFu, r, off);
            if (t < NW - off) r += n;
        }
        wtail[t] = r - q;                  // sum of warp totals AFTER warp t
    }
    __syncthreads();
    unsigned beyond = (p - s) + wtail[wid];
#pragma unroll
    for (int j = 0; j < B; j++) {
        unsigned incl = loc[j] + beyond;                          // count(>=d)
        unsigned cnt  = loc[j] - ((j < B - 1) ? loc[j + 1] : 0u); // hist[d]
        unsigned gt   = incl - cnt;                               // count(>d)
        if (incl >= k && gt < k) {
            *sh_digit = (unsigned)(base + j);
            *sh_k     = k - gt;
            *sh_cnt   = cnt;
        }
    }
    __syncthreads();
}

__global__ __launch_bounds__(TPB, 4)
void topk_mask_kernel(const float* __restrict__ x, float* __restrict__ out) {
    __shared__ float          row[ROWLEN];        // 32 KB
    __shared__ unsigned       hist[2048];         // 8 KB
    __shared__ unsigned       cand_key[CANDMAX];  // 4 KB
    __shared__ unsigned short cand_pos[CANDMAX];  // 2 KB
    __shared__ unsigned       wsum[NW];
    __shared__ unsigned       wtail[NW];
    __shared__ unsigned       sh_digit, sh_k, sh_cnt;
    __shared__ unsigned       ccnt;

    const int t    = threadIdx.x;
    const int lane = t & 31;
    const int wid  = t >> 5;
    const size_t row_off = (size_t)blockIdx.x * ROWLEN;
    const float4* __restrict__ px   = reinterpret_cast<const float4*>(x + row_off);
    float4*       __restrict__ po   = reinterpret_cast<float4*>(out + row_off);
    float*        __restrict__ pout = out + row_off;
    float4*                    prow = reinterpret_cast<float4*>(row);

    // ---- zero histogram ----
    reinterpret_cast<uint4*>(hist)[t] = make_uint4(0u, 0u, 0u, 0u);
    if (t == 0) ccnt = 0u;
    __syncthreads();

    // ---- sweep 1: global load -> smem stage + pass-1 histogram (11 bits) ----
#pragma unroll
    for (int i = 0; i < VPT; i++) {
        float4 a = px[t + i * TPB];
        prow[t + i * TPB] = a;
        atomicAdd(&hist[(__float_as_uint(a.x) & 0x7FFFFFFFu) >> 20], 1u);
        atomicAdd(&hist[(__float_as_uint(a.y) & 0x7FFFFFFFu) >> 20], 1u);
        atomicAdd(&hist[(__float_as_uint(a.z) & 0x7FFFFFFFu) >> 20], 1u);
        atomicAdd(&hist[(__float_as_uint(a.w) & 0x7FFFFFFFu) >> 20], 1u);
    }
    __syncthreads();

    unsigned k = KSEL;
    suffix_select<2048>(hist, k, t, lane, wid, wsum, wtail, &sh_digit, &sh_k, &sh_cnt);
    const unsigned d1 = sh_digit; k = sh_k;
    const unsigned C  = sh_cnt;          // elements with digit == d1

    // ---- sweep 2 (fused): final store of decided elems + pass-2 histogram
    //      + warp-aggregated candidate compaction ----
    reinterpret_cast<uint2*>(hist)[t] = make_uint2(0u, 0u);   // 1024 bins
    __syncthreads();
#pragma unroll
    for (int i = 0; i < VPT; i++) {
        float4 a = prow[t + i * TPB];
        float4 o;
        const float* fa = reinterpret_cast<const float*>(&a);
        float*       fo = reinterpret_cast<float*>(&o);
#pragma unroll
        for (int c = 0; c < 4; c++) {
            unsigned key = __float_as_uint(fa[c]) & 0x7FFFFFFFu;
            unsigned dig = key >> 20;
            // decided now: dig<d1 -> 0, dig>d1 -> keep. dig==d1 stored
            // provisionally as x; fixup zeroes losers later.
            fo[c] = (dig < d1) ? 0.0f : fa[c];
            bool isc = (dig == d1);
            if (isc) atomicAdd(&hist[(key >> 10) & 0x3FFu], 1u);
            unsigned m = __ballot_sync(0xFFFFFFFFu, isc);
            if (m) {                                   // warp-uniform branch
                int leader = __ffs(m) - 1;
                unsigned base = 0u;
                if (lane == leader) base = atomicAdd(&ccnt, (unsigned)__popc(m));
                base = __shfl_sync(0xFFFFFFFFu, base, leader);
                if (isc) {
                    unsigned idx = base + (unsigned)__popc(m & ((1u << lane) - 1u));
                    if (idx < CANDMAX) {
                        cand_key[idx] = key;
                        cand_pos[idx] = (unsigned short)(4 * (t + i * TPB) + c);
                    }
                }
            }
        }
        po[t + i * TPB] = o;
    }
    __syncthreads();
    suffix_select<1024>(hist, k, t, lane, wid, wsum, wtail, &sh_digit, &sh_k, &sh_cnt);
    const unsigned d2 = sh_digit; k = sh_k;
    const unsigned pref21 = (d1 << 10) | d2;     // == key >> 10 for survivors

    // ---- pass 3 histogram (bits [0,10)) ----
    reinterpret_cast<uint2*>(hist)[t] = make_uint2(0u, 0u);
    __syncthreads();
    if (C <= CANDMAX) {
        for (unsigned j = t; j < C; j += TPB) {
            unsigned key = cand_key[j];
            if ((key >> 10) == pref21)
                atomicAdd(&hist[key & 0x3FFu], 1u);
        }
    } else {
        // fallback: full-row sweep (not taken for Gaussian rows)
#pragma unroll
        for (int i = 0; i < VPT; i++) {
            float4 a = prow[t + i * TPB];
            const float* fa = reinterpret_cast<const float*>(&a);
#pragma unroll
            for (int c = 0; c < 4; c++) {
                unsigned key = __float_as_uint(fa[c]) & 0x7FFFFFFFu;
                if ((key >> 10) == pref21)
                    atomicAdd(&hist[key & 0x3FFu], 1u);
            }
        }
    }
    __syncthreads();
    suffix_select<1024>(hist, k, t, lane, wid, wsum, wtail, &sh_digit, &sh_k, &sh_cnt);

    const unsigned T = (pref21 << 10) | sh_digit;   // K-th largest |x| pattern

    // ---- fixup: zero candidates below T ----
    if (C <= CANDMAX) {
        for (unsigned j = t; j < C; j += TPB)
            if (cand_key[j] < T)
                pout[cand_pos[j]] = 0.0f;
    } else {
        // fallback: full-row fixup
#pragma unroll
        for (int i = 0; i < VPT; i++) {
            float4 a = prow[t + i * TPB];
            const float* fa = reinterpret_cast<const float*>(&a);
#pragma unroll
            for (int c = 0; c < 4; c++) {
                unsigned key = __float_as_uint(fa[c]) & 0x7FFFFFFFu;
                if ((key >> 20) == d1 && key < T)
                    pout[4 * (t + i * TPB) + c] = 0.0f;
            }
        }
    }
}

extern "C" void kernel_launch(void* const* d_in, const int* in_sizes, int n_in,
                              void* d_out, int out_size) {
    const float* x = (const float*)d_in[0];
    float* out = (float*)d_out;
    const int rows = in_sizes[0] / ROWLEN;   // 4096
    topk_mask_kernel<<<rows, TPB>>>(x, out);
}

// round 9
// speedup vs baseline: 1.0741x; 1.0741x over previous
#include <cuda_runtime.h>
#include <cstdint>

// TopK-magnitude masking per row. x: (4096, 8192) fp32, K = 819.
// out[r,c] = x[r,c] if |x[r,c]| >= (K-th largest |x| in row r) else 0.
//
// One CTA per row, 512 threads. The row lives in REGISTERS as 16 stripped
// 31-bit keys per thread + one packed sign word (value is reconstructed as
// key | sign<<31). No smem row buffer -> passes 2/3 and the epilogue are
// pure register loops. 3-pass radix select (11+10+10 bits), plain predicated
// shared atomics, 4-way replicated pass-1 histogram to cut ATOMS contention.

#define ROWLEN 8192
#define TPB    512
#define KSEL   819u
#define NW     (TPB / 32)   // 16 warps
#define NREP   4            // pass-1 histogram replicas

__global__ __launch_bounds__(TPB, 3)
void topk_mask_kernel(const float* __restrict__ x, float* __restrict__ out) {
    __shared__ unsigned hist[NREP * 2048];   // 32 KB
    __shared__ unsigned wsum[NW];
    __shared__ unsigned wtail[NW];
    __shared__ unsigned sh_digit, sh_k;

    const int t    = threadIdx.x;
    const int lane = t & 31;
    const int wid  = t >> 5;
    const size_t row_off = (size_t)blockIdx.x * ROWLEN;
    const uint4* __restrict__ px = reinterpret_cast<const uint4*>(x + row_off);
    uint4*       __restrict__ po = reinterpret_cast<uint4*>(out + row_off);

    // ---- zero all replicas (NREP*2048 words = 16 words/thread) ----
    {
        uint4 z = make_uint4(0u, 0u, 0u, 0u);
        uint4* h4 = reinterpret_cast<uint4*>(hist);
#pragma unroll
        for (int i = 0; i < NREP; i++) h4[t + i * TPB] = z;
    }
    __syncthreads();

    // ---- load row -> register keys + packed signs; pass-1 histogram ----
    unsigned key[16];
    unsigned signs = 0u;
    unsigned* hrep = &hist[(wid & (NREP - 1)) * 2048];
#pragma unroll
    for (int i = 0; i < 4; i++) {
        uint4 a = px[t + i * TPB];
        const unsigned b[4] = {a.x, a.y, a.z, a.w};
#pragma unroll
        for (int c = 0; c < 4; c++) {
            const int idx = i * 4 + c;
            unsigned kk = b[c] & 0x7FFFFFFFu;
            key[idx] = kk;
            signs |= (b[c] >> 31) << idx;
            atomicAdd(&hrep[kk >> 20], 1u);
        }
    }
    __syncthreads();

    unsigned k = KSEL;
    unsigned d1, d2;

    // =============== pass-1 select: 2048 bins, sum NREP replicas ===============
    {
        const int base = t * 4;
        unsigned loc[4];
        unsigned s = 0u;
#pragma unroll
        for (int j = 3; j >= 0; j--) {
            unsigned cnt = 0u;
#pragma unroll
            for (int r = 0; r < NREP; r++) cnt += hist[r * 2048 + base + j];
            s += cnt; loc[j] = s;
        }
        unsigned p = s;                      // warp suffix scan of chunk totals
#pragma unroll
        for (int off = 1; off < 32; off <<= 1) {
            unsigned n = __shfl_down_sync(0xFFFFFFFFu, p, off);
            if (lane < 32 - off) p += n;
        }
        if (lane == 0) wsum[wid] = p;
        __syncthreads();
        if (t < NW) {
            unsigned q = wsum[t];
            unsigned r = q;
#pragma unroll
            for (int off = 1; off < NW; off <<= 1) {
                unsigned n = __shfl_down_sync(0x0000FFFFu, r, off);
                if (t < NW - off) r += n;
            }
            wtail[t] = r - q;                // sum of warp totals AFTER warp t
        }
        __syncthreads();
        unsigned beyond = (p - s) + wtail[wid];
#pragma unroll
        for (int j = 0; j < 4; j++) {
            unsigned incl = loc[j] + beyond;
            unsigned cnt  = loc[j] - ((j < 3) ? loc[j + 1] : 0u);
            unsigned gt   = incl - cnt;
            if (incl >= k && gt < k) { sh_digit = (unsigned)(base + j); sh_k = k - gt; }
        }
        __syncthreads();
        d1 = sh_digit; k = sh_k;
    }

    // =============== pass 2: bits [10,20), register sweep, 1024 bins ===============
    reinterpret_cast<uint2*>(hist)[t] = make_uint2(0u, 0u);
    __syncthreads();
#pragma unroll
    for (int idx = 0; idx < 16; idx++) {
        unsigned kk = key[idx];
        if ((kk >> 20) == d1)
            atomicAdd(&hist[(kk >> 10) & 0x3FFu], 1u);
    }
    __syncthreads();
    {
        const int base = t * 2;
        unsigned loc[2];
        unsigned s = 0u;
#pragma unroll
        for (int j = 1; j >= 0; j--) { s += hist[base + j]; loc[j] = s; }
        unsigned p = s;
#pragma unroll
        for (int off = 1; off < 32; off <<= 1) {
            unsigned n = __shfl_down_sync(0xFFFFFFFFu, p, off);
            if (lane < 32 - off) p += n;
        }
        if (lane == 0) wsum[wid] = p;
        __syncthreads();
        if (t < NW) {
            unsigned q = wsum[t];
            unsigned r = q;
#pragma unroll
            for (int off = 1; off < NW; off <<= 1) {
                unsigned n = __shfl_down_sync(0x0000FFFFu, r, off);
                if (t < NW - off) r += n;
            }
            wtail[t] = r - q;
        }
        __syncthreads();
        unsigned beyond = (p - s) + wtail[wid];
#pragma unroll
        for (int j = 0; j < 2; j++) {
            unsigned incl = loc[j] + beyond;
            unsigned cnt  = loc[j] - ((j < 1) ? loc[j + 1] : 0u);
            unsigned gt   = incl - cnt;
            if (incl >= k && gt < k) { sh_digit = (unsigned)(base + j); sh_k = k - gt; }
        }
        __syncthreads();
        d2 = sh_digit; k = sh_k;
    }

    // =============== pass 3: bits [0,10), register sweep, 1024 bins ===============
    const unsigned pref21 = (d1 << 10) | d2;     // == key >> 10 for survivors
    reinterpret_cast<uint2*>(hist)[t] = make_uint2(0u, 0u);
    __syncthreads();
#pragma unroll
    for (int idx = 0; idx < 16; idx++) {
        unsigned kk = key[idx];
        if ((kk >> 10) == pref21)
            atomicAdd(&hist[kk & 0x3FFu], 1u);
    }
    __syncthreads();
    {
        const int base = t * 2;
        unsigned loc[2];
        unsigned s = 0u;
#pragma unroll
        for (int j = 1; j >= 0; j--) { s += hist[base + j]; loc[j] = s; }
        unsigned p = s;
#pragma unroll
        for (int off = 1; off < 32; off <<= 1) {
            unsigned n = __shfl_down_sync(0xFFFFFFFFu, p, off);
            if (lane < 32 - off) p += n;
        }
        if (lane == 0) wsum[wid] = p;
        __syncthreads();
        if (t < NW) {
            unsigned q = wsum[t];
            unsigned r = q;
#pragma unroll
            for (int off = 1; off < NW; off <<= 1) {
                unsigned n = __shfl_down_sync(0x0000FFFFu, r, off);
                if (t < NW - off) r += n;
            }
            wtail[t] = r - q;
        }
        __syncthreads();
        unsigned beyond = (p - s) + wtail[wid];
#pragma unroll
        for (int j = 0; j < 2; j++) {
            unsigned incl = loc[j] + beyond;
            unsigned cnt  = loc[j] - ((j < 1) ? loc[j + 1] : 0u);
            unsigned gt   = incl - cnt;
            if (incl >= k && gt < k) sh_digit = (unsigned)(base + j);
        }
        __syncthreads();
    }

    const unsigned T = (pref21 << 10) | sh_digit;   // K-th largest |x| pattern

    // ---- epilogue: reconstruct value from key+sign, masked float4 store ----
#pragma unroll
    for (int i = 0; i < 4; i++) {
        unsigned o[4];
#pragma unroll
        for (int c = 0; c < 4; c++) {
            const int idx = i * 4 + c;
            unsigned kk = key[idx];
            unsigned bits = kk | (((signs >> idx) & 1u) << 31);
            o[c] = (kk < T) ? 0u : bits;
        }
        po[t + i * TPB] = make_uint4(o[0], o[1], o[2], o[3]);
    }
}

extern "C" void kernel_launch(void* const* d_in, const int* in_sizes, int n_in,
                              void* d_out, int out_size) {
    const float* x = (const float*)d_in[0];
    float* out = (float*)d_out;
    const int rows = in_sizes[0] / ROWLEN;   // 4096
    topk_mask_kernel<<<rows, TPB>>>(x, out);
}